// round 1
// baseline (speedup 1.0000x reference)
#include <cuda_runtime.h>
#include <math.h>

// PerformanceModel_4346506903896
// out[i] = prod_j sigmoid( (ub[j] - logit(bin_centers[idx[i][j]])) / (ub[j]-lb[j]+1e-4) )
//
// Inputs (metadata order):
//   d_in[0]: bin_centers                     float32 [1024]
//   d_in[1]: observation_probability_index   int32   [16777216, 3]
//   d_in[2]: lb                              float32 [3]
//   d_in[3]: ub                              float32 [3]
//   d_in[4]: operator_number                 (scalar, unused by the math)
// Output: float32 [16777216]

#define N_BINS 1024
#define BLOCK  256

__global__ __launch_bounds__(BLOCK)
void pm_lut_kernel(const float* __restrict__ bin_centers,
                   const int4*  __restrict__ idx4,     // indices viewed as int4
                   const float* __restrict__ lb,
                   const float* __restrict__ ub,
                   float4*      __restrict__ out4,
                   long long    n_groups)              // n_rows / 4
{
    // 12 KB shared LUT: tab[j][bin] = sigmoid((ub[j]-logit(c_bin)) * inv_den_j)
    __shared__ float tab0[N_BINS];
    __shared__ float tab1[N_BINS];
    __shared__ float tab2[N_BINS];

    const float ub0 = ub[0], ub1 = ub[1], ub2 = ub[2];
    const float inv0 = 1.0f / (ub0 - lb[0] + 1e-4f);
    const float inv1 = 1.0f / (ub1 - lb[1] + 1e-4f);
    const float inv2 = 1.0f / (ub2 - lb[2] + 1e-4f);

    for (int b = threadIdx.x; b < N_BINS; b += BLOCK) {
        float c  = bin_centers[b];
        float lg = logf(c / (1.0f - c));          // finite: c in (0.01, 0.99)
        tab0[b] = 1.0f / (1.0f + expf(-(ub0 - lg) * inv0));
        tab1[b] = 1.0f / (1.0f + expf(-(ub1 - lg) * inv1));
        tab2[b] = 1.0f / (1.0f + expf(-(ub2 - lg) * inv2));
    }
    __syncthreads();

    long long g = (long long)blockIdx.x * BLOCK + threadIdx.x;  // one group = 4 rows
    if (g >= n_groups) return;

    // 4 rows x 3 int32 indices = 3 contiguous int4 loads (fully coalesced 48B)
    const long long base = g * 3;
    int4 t0 = idx4[base + 0];
    int4 t1 = idx4[base + 1];
    int4 t2 = idx4[base + 2];

    float4 r;
    r.x = tab0[t0.x] * tab1[t0.y] * tab2[t0.z];
    r.y = tab0[t0.w] * tab1[t1.x] * tab2[t1.y];
    r.z = tab0[t1.z] * tab1[t1.w] * tab2[t2.x];
    r.w = tab0[t2.y] * tab1[t2.z] * tab2[t2.w];

    out4[g] = r;
}

extern "C" void kernel_launch(void* const* d_in, const int* in_sizes, int n_in,
                              void* d_out, int out_size)
{
    const float* bin_centers = (const float*)d_in[0];
    const int4*  idx4        = (const int4*) d_in[1];
    const float* lb          = (const float*)d_in[2];
    const float* ub          = (const float*)d_in[3];
    float*       out         = (float*)d_out;

    long long n_rows   = (long long)out_size;          // 16,777,216
    long long n_groups = n_rows / 4;                   // divisible by 4
    long long n_blocks = (n_groups + BLOCK - 1) / BLOCK;

    pm_lut_kernel<<<(unsigned)n_blocks, BLOCK>>>(
        bin_centers, idx4, lb, ub, (float4*)d_out, n_groups);
}

// round 6
// speedup vs baseline: 1.3283x; 1.3283x over previous
#include <cuda_runtime.h>
#include <math.h>

// PerformanceModel_4346506903896
// out[i] = prod_j sigmoid( (ub[j] - logit(bin_centers[idx[i][j]])) / (ub[j]-lb[j]+1e-4) )
//
// R2: 8 rows per thread. 6 int4 index loads + 2 float4 stores per thread,
// all base+immediate addressing; no bounds predicate (exact division).
//
// Inputs (metadata order):
//   d_in[0]: bin_centers                     float32 [1024]
//   d_in[1]: observation_probability_index   int32   [16777216, 3]
//   d_in[2]: lb                              float32 [3]
//   d_in[3]: ub                              float32 [3]
//   d_in[4]: operator_number                 (unused by the math)
// Output: float32 [16777216]

#define N_BINS   1024
#define BLOCK    256
#define ROWS_PT  8                       // rows per thread
#define N_ROWS   16777216LL

__global__ __launch_bounds__(BLOCK)
void pm_lut8_kernel(const float* __restrict__ bin_centers,
                    const int4*  __restrict__ idx4,   // indices viewed as int4
                    const float* __restrict__ lb,
                    const float* __restrict__ ub,
                    float4*      __restrict__ out4)
{
    // 12 KB shared LUT: tab[j][bin] = sigmoid((ub[j]-logit(c_bin)) * inv_den_j)
    __shared__ float tab0[N_BINS];
    __shared__ float tab1[N_BINS];
    __shared__ float tab2[N_BINS];

    {
        const float ub0 = ub[0], ub1 = ub[1], ub2 = ub[2];
        const float inv0 = 1.0f / (ub0 - lb[0] + 1e-4f);
        const float inv1 = 1.0f / (ub1 - lb[1] + 1e-4f);
        const float inv2 = 1.0f / (ub2 - lb[2] + 1e-4f);
        #pragma unroll
        for (int k = 0; k < N_BINS / BLOCK; ++k) {
            int b = k * BLOCK + threadIdx.x;
            float c  = bin_centers[b];
            float lg = logf(c / (1.0f - c));        // finite: c in (0.01, 0.99)
            tab0[b] = 1.0f / (1.0f + expf(-(ub0 - lg) * inv0));
            tab1[b] = 1.0f / (1.0f + expf(-(ub1 - lg) * inv1));
            tab2[b] = 1.0f / (1.0f + expf(-(ub2 - lg) * inv2));
        }
    }
    __syncthreads();

    // one thread = 8 rows = 24 int32 indices = 6 int4 loads, 2 float4 stores.
    const long long t = (long long)blockIdx.x * BLOCK + threadIdx.x;

    const int4* ip = idx4 + t * 6;          // base + immediate offsets below
    int4 a = ip[0];                          // rows 0,1: i00 i01 i02 | i10
    int4 b = ip[1];                          //           i11 i12 | i20 i21
    int4 c = ip[2];                          //           i22 | i30 i31 i32
    int4 d = ip[3];                          // rows 4..7 same pattern
    int4 e = ip[4];
    int4 f = ip[5];

    float4 r0, r1;
    r0.x = tab0[a.x] * tab1[a.y] * tab2[a.z];
    r0.y = tab0[a.w] * tab1[b.x] * tab2[b.y];
    r0.z = tab0[b.z] * tab1[b.w] * tab2[c.x];
    r0.w = tab0[c.y] * tab1[c.z] * tab2[c.w];
    r1.x = tab0[d.x] * tab1[d.y] * tab2[d.z];
    r1.y = tab0[d.w] * tab1[e.x] * tab2[e.y];
    r1.z = tab0[e.z] * tab1[e.w] * tab2[f.x];
    r1.w = tab0[f.y] * tab1[f.z] * tab2[f.w];

    float4* op = out4 + t * 2;
    op[0] = r0;
    op[1] = r1;
}

extern "C" void kernel_launch(void* const* d_in, const int* in_sizes, int n_in,
                              void* d_out, int out_size)
{
    const float* bin_centers = (const float*)d_in[0];
    const int4*  idx4        = (const int4*) d_in[1];
    const float* lb          = (const float*)d_in[2];
    const float* ub          = (const float*)d_in[3];

    // 16,777,216 rows / 8 rows-per-thread / 256 threads = 8192 blocks exactly
    long long n_threads = N_ROWS / ROWS_PT;
    unsigned  n_blocks  = (unsigned)(n_threads / BLOCK);

    pm_lut8_kernel<<<n_blocks, BLOCK>>>(
        bin_centers, idx4, lb, ub, (float4*)d_out);
}